// round 16
// baseline (speedup 1.0000x reference)
#include <cuda_runtime.h>
#include <cuda_fp16.h>
#include <math.h>
#include <stdint.h>

// ---------------- problem constants ----------------
#define BATCH 2048
#define SIZE_D 2048
#define HID 1024
#define NC 17
#define OUTW (SIZE_D * NC)   // 34816
#define NTOT (BATCH * SIZE_D)
#define EPS_C 1e-6f
#define NSTATBLK (NTOT / 4 / 256)              // 4096
#define NW1T ((HID / 64) * (SIZE_D / 64))      // 512
#define NW2T ((OUTW / 64) * (HID / 64))        // 8704

// ---------------- GEMM tiling: 128x128 block, GBK=64 ----------------
#define GBM 128
#define GBK 64
#define GSTAGES 3
#define TILE_BYTES 16384                       // 128 rows x 128B
#define STAGE_B (2 * TILE_BYTES)               // 32768
#define GEMM_SMEM (GSTAGES * STAGE_B)          // 98304 -> 2 CTAs/SM

// spline chunk: 256 sites x 17 halfs = 8704 bytes = 544 x 16B
#define SCHUNK_B (256 * NC * 2)
#define SCHUNK_16 (SCHUNK_B / 16)              // 544

// ---------------- device scratch ----------------
__device__ __half g_xh[(size_t)NTOT];
__device__ __half g_w1t[(size_t)HID * SIZE_D];
__device__ __half g_h[(size_t)BATCH * HID];
__device__ __half g_w2t[(size_t)OUTW * HID];
__device__ __half g_net[(size_t)BATCH * OUTW];
__device__ float g_colsum[HID];          // zero at load; re-zeroed by spline
__device__ float g_part_s[NSTATBLK];
__device__ float g_part_ss[NSTATBLK];
__device__ float g_stats[2];
__device__ unsigned int g_ctr;

// ---------------- PTX helpers ----------------
__device__ __forceinline__ uint32_t smem_u32(const void* p) {
    uint32_t a;
    asm("{ .reg .u64 t; cvta.to.shared.u64 t, %1; cvt.u32.u64 %0, t; }"
        : "=r"(a) : "l"(p));
    return a;
}
__device__ __forceinline__ void cp_async16(uint32_t sa, const void* ga) {
    asm volatile("cp.async.cg.shared.global [%0], [%1], 16;"
                 :: "r"(sa), "l"(ga) : "memory");
}
__device__ __forceinline__ void cp_commit() {
    asm volatile("cp.async.commit_group;" ::: "memory");
}
template <int N>
__device__ __forceinline__ void cp_wait() {
    asm volatile("cp.async.wait_group %0;" :: "n"(N) : "memory");
}
__device__ __forceinline__ void ldmatrix_x4(uint32_t* r, uint32_t addr) {
    asm volatile("ldmatrix.sync.aligned.m8n8.x4.shared.b16 {%0,%1,%2,%3}, [%4];"
                 : "=r"(r[0]), "=r"(r[1]), "=r"(r[2]), "=r"(r[3])
                 : "r"(addr));
}
__device__ __forceinline__ void mma16816(float* c, const uint32_t* a,
                                         uint32_t b0, uint32_t b1) {
    asm volatile(
        "mma.sync.aligned.m16n8k16.row.col.f32.f16.f16.f32 "
        "{%0,%1,%2,%3}, {%4,%5,%6,%7}, {%8,%9}, {%0,%1,%2,%3};"
        : "+f"(c[0]), "+f"(c[1]), "+f"(c[2]), "+f"(c[3])
        : "r"(a[0]), "r"(a[1]), "r"(a[2]), "r"(a[3]), "r"(b0), "r"(b1));
}
// 128B-row swizzle: 16B chunk index XOR (row & 7)
__device__ __forceinline__ uint32_t sw128(int row, int ch) {
    return ((uint32_t)row << 7) + ((uint32_t)((ch ^ (row & 7)) & 7) << 4);
}
__device__ __forceinline__ float fast_tanh(float x) {
    float e = __expf(2.0f * x);
    return 1.0f - 2.0f / (e + 1.0f);
}

// ---------------- fused prep: stats + w1t + w2t ----------------
__device__ __forceinline__ void transpose_tile(
    const float* __restrict__ src, __half* __restrict__ dst,
    float* smembuf, int K, int N, int n0, int k0, int docolsum, int tid) {
    float (*t)[65] = (float (*)[65])smembuf;
    const int lr = tid >> 4;
    const int lc = (tid & 15) * 4;
#pragma unroll
    for (int i = 0; i < 64; i += 16) {
        float4 v = *(const float4*)(src + (size_t)(k0 + lr + i) * N + n0 + lc);
        t[lr + i][lc + 0] = v.x;
        t[lr + i][lc + 1] = v.y;
        t[lr + i][lc + 2] = v.z;
        t[lr + i][lc + 3] = v.w;
    }
    __syncthreads();
    if (docolsum && tid < 64) {
        float s = 0.f;
#pragma unroll
        for (int r = 0; r < 64; r++) s += t[r][tid];
        atomicAdd(&g_colsum[n0 + tid], s);
    }
    const int wid = tid >> 5;
    const int lane = tid & 31;
#pragma unroll
    for (int i = 0; i < 64; i += 8) {
        const int r = wid + i;
        const int k = lane * 2;
        __half2 hp = {__float2half_rn(t[k][r]), __float2half_rn(t[k + 1][r])};
        *(__half2*)(dst + (size_t)(n0 + r) * K + k0 + k) = hp;
    }
}

__global__ __launch_bounds__(256)
void prep_fused(const float* __restrict__ xp, __half* __restrict__ xh,
                const float* __restrict__ w1, __half* __restrict__ w1t,
                const float* __restrict__ w2, __half* __restrict__ w2t) {
    __shared__ float smembuf[64 * 65];
    __shared__ int slast;
    const int tid = threadIdx.x;

    if (blockIdx.x < NSTATBLK) {
        const int i = blockIdx.x * 256 + tid;
        float4 v = ((const float4*)xp)[i];

        __half2 p0 = {__float2half_rn(v.x), __float2half_rn(v.y)};
        __half2 p1 = {__float2half_rn(v.z), __float2half_rn(v.w)};
        uint2 hv = {*(uint32_t*)&p0, *(uint32_t*)&p1};
        ((uint2*)xh)[i] = hv;

        float* shs = smembuf;
        float* shss = smembuf + 256;
        float s = v.x + v.y + v.z + v.w;
        float ss = v.x * v.x + v.y * v.y + v.z * v.z + v.w * v.w;
        shs[tid] = s; shss[tid] = ss;
        __syncthreads();
        for (int o = 128; o > 0; o >>= 1) {
            if (tid < o) { shs[tid] += shs[tid + o]; shss[tid] += shss[tid + o]; }
            __syncthreads();
        }
        if (tid == 0) {
            g_part_s[blockIdx.x] = shs[0];
            g_part_ss[blockIdx.x] = shss[0];
            __threadfence();
            unsigned int old = atomicAdd(&g_ctr, 1u);
            slast = (old == NSTATBLK - 1) ? 1 : 0;
        }
        __syncthreads();
        if (slast) {
            __threadfence();
            float fs = 0.f, fss = 0.f;
            for (int k = tid; k < NSTATBLK; k += 256) {
                fs += g_part_s[k]; fss += g_part_ss[k];
            }
            shs[tid] = fs; shss[tid] = fss;
            __syncthreads();
            for (int o = 128; o > 0; o >>= 1) {
                if (tid < o) { shs[tid] += shs[tid + o]; shss[tid] += shss[tid + o]; }
                __syncthreads();
            }
            if (tid == 0) {
                float S = shs[0], SS = shss[0];
                float mean = S / (float)NTOT;
                float var = (SS - S * mean) / (float)(NTOT - 1);
                g_stats[0] = mean;
                g_stats[1] = rsqrtf(var);
                g_ctr = 0;
            }
        }
    } else if (blockIdx.x < NSTATBLK + NW1T) {
        const int bid = blockIdx.x - NSTATBLK;
        const int n0 = (bid & 15) * 64;
        const int k0 = (bid >> 4) * 64;
        transpose_tile(w1, w1t, smembuf, SIZE_D, HID, n0, k0, 1, tid);
    } else {
        const int bid = blockIdx.x - NSTATBLK - NW1T;
        const int n0 = (bid % (OUTW / 64)) * 64;
        const int k0 = (bid / (OUTW / 64)) * 64;
        transpose_tile(w2, w2t, smembuf, HID, OUTW, n0, k0, 0, tid);
    }
}

// ---------------- fp16 GEMM: 128x128, GBK=64, B-fragment double buffer -----
template <int EPI>
__global__ __launch_bounds__(256, 2)
void gemm_fp16(const __half* __restrict__ A,
               const __half* __restrict__ B,
               const float* __restrict__ bias,
               const float* __restrict__ colsum,
               __half* __restrict__ C,
               int K, int Nout, int KTILES) {
    extern __shared__ __align__(128) char smem[];
    const uint32_t sb = smem_u32(smem);
    const int tid = threadIdx.x;
    const int wid = tid >> 5;
    const int lane = tid & 31;
    const int wm = wid & 3;
    const int wn = wid >> 2;
    const int m0 = blockIdx.x * GBM;
    const int n0 = blockIdx.y * 128;

    const int rr = tid >> 3;
    const int cc = tid & 7;
    const uint32_t so = sw128(rr, cc);

    const __half* pA = A + (size_t)(m0 + rr) * K + cc * 8;
    const __half* pB = B + (size_t)(n0 + rr) * K + cc * 8;
    const size_t k32 = (size_t)32 * K;
    const size_t k64 = (size_t)64 * K;
    const size_t k96 = (size_t)96 * K;

    auto load_stage_at = [&](uint32_t base) {
        cp_async16(base + so,          pA);
        cp_async16(base + so + 4096,   pA + k32);
        cp_async16(base + so + 8192,   pA + k64);
        cp_async16(base + so + 12288,  pA + k96);
        const uint32_t bb = base + TILE_BYTES;
        cp_async16(bb + so,            pB);
        cp_async16(bb + so + 4096,     pB + k32);
        cp_async16(bb + so + 8192,     pB + k64);
        cp_async16(bb + so + 12288,    pB + k96);
        pA += GBK; pB += GBK;
    };

    const int lrow = lane & 15;
    const int lhalf = lane >> 4;
    uint32_t offA[4], offB[4];
#pragma unroll
    for (int k16 = 0; k16 < 4; k16++) {
        const int kc = k16 * 2 + lhalf;
        offA[k16] = sw128(wm * 32 + lrow, kc);
        offB[k16] = TILE_BYTES + sw128(wn * 64 + lrow, kc);
    }

    float acc[2][8][4];
#pragma unroll
    for (int a = 0; a < 2; a++)
#pragma unroll
        for (int b = 0; b < 8; b++)
#pragma unroll
            for (int c = 0; c < 4; c++) acc[a][b][c] = 0.f;

#pragma unroll
    for (int s = 0; s < GSTAGES - 1; s++) {
        load_stage_at(sb + s * STAGE_B);
        cp_commit();
    }

    int cs = 0;
    int ls = GSTAGES - 1;
    for (int kt = 0; kt < KTILES; kt++) {
        cp_wait<GSTAGES - 2>();
        __syncthreads();

        if (kt + GSTAGES - 1 < KTILES) load_stage_at(sb + ls * STAGE_B);
        cp_commit();

        const uint32_t st = sb + cs * STAGE_B;
#pragma unroll
        for (int k16 = 0; k16 < 4; k16++) {
            const uint32_t aB = st + offA[k16];
            const uint32_t bB = st + offB[k16];
            uint32_t afr[2][4];
            ldmatrix_x4(afr[0], aB);
            ldmatrix_x4(afr[1], aB + 2048);

            // B-fragment double buffer: load g0,g1 up front; while the 16
            // MMAs of group g run, refill the consumed buffer with g+2.
            uint32_t bfr[2][4];
            ldmatrix_x4(bfr[0], bB);            // g=0
            ldmatrix_x4(bfr[1], bB + 2048);     // g=1

            // g=0
#pragma unroll
            for (int mt = 0; mt < 2; mt++)
#pragma unroll
                for (int p = 0; p < 2; p++)
                    mma16816(acc[mt][0 + p], afr[mt], bfr[0][p], bfr[0][2 + p]);
            ldmatrix_x4(bfr[0], bB + 2 * 2048); // g=2 refill

            // g=1
#pragma unroll
            for (int mt = 0; mt < 2; mt++)
#pragma unroll
                for (int p = 0; p < 2; p++)
                    mma16816(acc[mt][2 + p], afr[mt], bfr[1][p], bfr[1][2 + p]);
            ldmatrix_x4(bfr[1], bB + 3 * 2048); // g=3 refill

            // g=2
#pragma unroll
            for (int mt = 0; mt < 2; mt++)
#pragma unroll
                for (int p = 0; p < 2; p++)
                    mma16816(acc[mt][4 + p], afr[mt], bfr[0][p], bfr[0][2 + p]);

            // g=3
#pragma unroll
            for (int mt = 0; mt < 2; mt++)
#pragma unroll
                for (int p = 0; p < 2; p++)
                    mma16816(acc[mt][6 + p], afr[mt], bfr[1][p], bfr[1][2 + p]);
        }
        cs = (cs + 1 == GSTAGES) ? 0 : cs + 1;
        ls = (ls + 1 == GSTAGES) ? 0 : ls + 1;
    }

    float mean = 0.f, invstd = 1.f;
    if (EPI == 0) { mean = g_stats[0]; invstd = g_stats[1]; }

    const int r_base = m0 + wm * 32 + (lane >> 2);
    const int c_base = n0 + wn * 64 + (lane & 3) * 2;

#pragma unroll
    for (int mt = 0; mt < 2; mt++) {
#pragma unroll
        for (int nf = 0; nf < 8; nf++) {
            const int col = c_base + nf * 8;
            float be0, be1;
            if (EPI == 0) {
                be0 = bias[col]     - mean * invstd * colsum[col];
                be1 = bias[col + 1] - mean * invstd * colsum[col + 1];
            } else {
                be0 = bias[col];
                be1 = bias[col + 1];
            }
#pragma unroll
            for (int hh = 0; hh < 2; hh++) {
                const int row = r_base + mt * 16 + hh * 8;
                float v0 = acc[mt][nf][hh * 2 + 0];
                float v1 = acc[mt][nf][hh * 2 + 1];
                if (EPI == 0) {
                    v0 = fast_tanh(fmaf(invstd, v0, be0));
                    v1 = fast_tanh(fmaf(invstd, v1, be1));
                } else {
                    v0 = fast_tanh(v0 + be0);
                    v1 = fast_tanh(v1 + be1);
                }
                __half2 hp = {__float2half_rn(v0), __float2half_rn(v1)};
                *(__half2*)(C + (size_t)row * Nout + col) = hp;
            }
        }
    }
}

// ---------------- spline: cp.async double-buffered chunks ----------------
__global__ __launch_bounds__(256)
void spline_kernel(const __half* __restrict__ net, const float* __restrict__ x_in,
                   const float* __restrict__ logd, float* __restrict__ phi_out,
                   float* __restrict__ log_out) {
    const int b = blockIdx.x;
    const int tid = threadIdx.x;
    const char* row = (const char*)(net + (size_t)b * OUTW);

    __shared__ __align__(16) __half sh[2][256 * NC];
    __shared__ float red[256];

    if (b < 4) g_colsum[b * 256 + tid] = 0.f;

    const uint32_t sbase0 = smem_u32(&sh[0][0]);
    const uint32_t sbase1 = smem_u32(&sh[1][0]);

    auto issue_chunk = [&](int buf, int chunk) {
        const uint32_t sb_ = buf ? sbase1 : sbase0;
        const char* src = row + (size_t)chunk * SCHUNK_B;
        cp_async16(sb_ + tid * 16, src + tid * 16);
        cp_async16(sb_ + (tid + 256) * 16, src + (size_t)(tid + 256) * 16);
        if (tid < SCHUNK_16 - 512)
            cp_async16(sb_ + (tid + 512) * 16, src + (size_t)(tid + 512) * 16);
        cp_commit();
    };

    issue_chunk(0, 0);

    float lsum = 0.f;

    for (int chunk = 0; chunk < 8; chunk++) {
        cp_wait<0>();
        __syncthreads();

        if (chunk < 7) issue_chunk((chunk + 1) & 1, chunk + 1);

        const __half* p = &sh[chunk & 1][tid * NC];

        float hr[9], wr[8];
#pragma unroll
        for (int c = 0; c < 9; c++) hr[c] = __half2float(p[c]);
#pragma unroll
        for (int c = 0; c < 8; c++) wr[c] = __half2float(p[9 + c]);

        float m = wr[0];
#pragma unroll
        for (int c = 1; c < 8; c++) m = fmaxf(m, wr[c]);
        float wn[8];
        float wsum = 0.f;
#pragma unroll
        for (int c = 0; c < 8; c++) { wn[c] = __expf(wr[c] - m); wsum += wn[c]; }
        float winv = 1.0f / wsum;
#pragma unroll
        for (int c = 0; c < 8; c++) wn[c] *= winv;

        float eh[9];
#pragma unroll
        for (int c = 0; c < 9; c++) eh[c] = __expf(hr[c]);
        float denom = 0.f;
#pragma unroll
        for (int c = 0; c < 8; c++) denom += 0.5f * wn[c] * (eh[c] + eh[c + 1]);
        float dinv = 1.0f / denom;
        float hn[9];
#pragma unroll
        for (int c = 0; c < 9; c++) hn[c] = eh[c] * dinv;

        const int s = chunk * 256 + tid;
        const float x = x_in[(size_t)b * SIZE_D + s] * 0.31830988618379067154f;

        float cum = 0.f, phicum = 0.f;
        float wk = wn[0], hk = hn[0], hk1 = hn[1];
        float xkm1 = -EPS_C, phikm1 = 0.f;
#pragma unroll
        for (int i = 0; i < 7; i++) {
            float trap = 0.5f * wn[i] * (hn[i] + hn[i + 1]);
            cum += wn[i];
            phicum += trap;
            bool c = (cum < x);
            wk     = c ? wn[i + 1] : wk;
            hk     = c ? hn[i + 1] : hk;
            hk1    = c ? hn[i + 2] : hk1;
            xkm1   = c ? cum      : xkm1;
            phikm1 = c ? phicum   : phikm1;
        }

        float alpha = (x - xkm1) / wk;
        float phi = phikm1 + alpha * hk * wk
                  + 0.5f * alpha * alpha * (hk1 - hk) * wk;
        phi_out[(size_t)b * SIZE_D + s] = phi;
        lsum += __logf(hk + alpha * (hk1 - hk));
    }

    red[tid] = lsum;
    __syncthreads();
    for (int o = 128; o > 0; o >>= 1) {
        if (tid < o) red[tid] += red[tid + o];
        __syncthreads();
    }
    if (tid == 0) log_out[b] = logd[b] - red[0];
}

// ---------------- launch ----------------
extern "C" void kernel_launch(void* const* d_in, const int* in_sizes, int n_in,
                              void* d_out, int out_size) {
    (void)in_sizes; (void)n_in; (void)out_size;
    const float* x_in      = (const float*)d_in[0];
    const float* x_passive = (const float*)d_in[1];
    const float* log_dens  = (const float*)d_in[2];
    const float* w1        = (const float*)d_in[3];
    const float* b1        = (const float*)d_in[4];
    const float* w2        = (const float*)d_in[5];
    const float* b2        = (const float*)d_in[6];

    float* out_phi = (float*)d_out;
    float* out_log = (float*)d_out + (size_t)NTOT;

    __half *xh, *w1t, *hbuf, *w2t, *nbuf;
    float *csum;
    cudaGetSymbolAddress((void**)&xh, g_xh);
    cudaGetSymbolAddress((void**)&w1t, g_w1t);
    cudaGetSymbolAddress((void**)&hbuf, g_h);
    cudaGetSymbolAddress((void**)&w2t, g_w2t);
    cudaGetSymbolAddress((void**)&nbuf, g_net);
    cudaGetSymbolAddress((void**)&csum, g_colsum);

    cudaFuncSetAttribute((const void*)gemm_fp16<0>,
                         cudaFuncAttributeMaxDynamicSharedMemorySize, GEMM_SMEM);
    cudaFuncSetAttribute((const void*)gemm_fp16<1>,
                         cudaFuncAttributeMaxDynamicSharedMemorySize, GEMM_SMEM);

    // 1) fused prep: stats(+finalize) + x fp16 + w1t(+colsum) + w2t
    prep_fused<<<NSTATBLK + NW1T + NW2T, 256>>>(x_passive, xh, w1, w1t, w2, w2t);
    // 2) GEMM1: h = tanh(xs @ w1 + b1) -> fp16   K=2048, KTILES=32
    gemm_fp16<0><<<dim3(BATCH / GBM, HID / 128), 256, GEMM_SMEM>>>(
        xh, w1t, b1, csum, hbuf, SIZE_D, HID, SIZE_D / GBK);
    // 3) GEMM2: net = tanh(h @ w2 + b2) -> fp16  K=1024, KTILES=16
    gemm_fp16<1><<<dim3(BATCH / GBM, OUTW / 128), 256, GEMM_SMEM>>>(
        hbuf, w2t, b2, nullptr, nbuf, HID, OUTW, HID / GBK);
    // 4) spline: cp.async double-buffered + per-row log reduction
    spline_kernel<<<BATCH, 256>>>(nbuf, x_in, log_dens, out_phi, out_log);
}